// round 1
// baseline (speedup 1.0000x reference)
#include <cuda_runtime.h>
#include <cuda_bf16.h>
#include <math.h>

// Problem constants
#define TSEQ 2048
#define DMODEL 2048
#define HQ 32
#define HKV 8
#define DHEAD 64
#define DKV (HKV * DHEAD)   // 512

// Scratch (device globals: allocation-free rule)
__device__ float g_q[TSEQ * DMODEL];     // (t, hq*64)
__device__ float g_k[TSEQ * DKV];        // (t, hkv*64)
__device__ float g_v[TSEQ * DKV];        // (t, hkv*64)
__device__ float g_attn[TSEQ * DMODEL];  // (t, hq*64)

// ---------------------------------------------------------------------------
// Generic 128x128x16 SGEMM tile body: C[m][n] = sum_k A[m][k] * B[n][k]
// A: row-major (128 rows x K), Bb: row-major (128 rows x K), Cb: row stride ldc
// 256 threads, 8x8 per-thread micro-tile.
// ---------------------------------------------------------------------------
__device__ __forceinline__ void gemm_tile(const float* __restrict__ Ab,
                                          const float* __restrict__ Bb,
                                          float* __restrict__ Cb,
                                          int K, int ldc) {
    __shared__ float As[16][132];
    __shared__ float Bs[16][132];

    int tid = threadIdx.x;
    int tx = tid & 15;
    int ty = tid >> 4;

    float acc[8][8];
#pragma unroll
    for (int i = 0; i < 8; ++i)
#pragma unroll
        for (int j = 0; j < 8; ++j) acc[i][j] = 0.0f;

    for (int k0 = 0; k0 < K; k0 += 16) {
#pragma unroll
        for (int it = 0; it < 2; ++it) {
            int slot = tid + it * 256;          // 512 float4 slots
            int row = slot >> 2;                // 0..127
            int c4 = (slot & 3) * 4;            // 0,4,8,12
            float4 va = *reinterpret_cast<const float4*>(Ab + (size_t)row * K + k0 + c4);
            As[c4 + 0][row] = va.x;
            As[c4 + 1][row] = va.y;
            As[c4 + 2][row] = va.z;
            As[c4 + 3][row] = va.w;
            float4 vb = *reinterpret_cast<const float4*>(Bb + (size_t)row * K + k0 + c4);
            Bs[c4 + 0][row] = vb.x;
            Bs[c4 + 1][row] = vb.y;
            Bs[c4 + 2][row] = vb.z;
            Bs[c4 + 3][row] = vb.w;
        }
        __syncthreads();

#pragma unroll
        for (int k = 0; k < 16; ++k) {
            float a[8], b[8];
            *reinterpret_cast<float4*>(a)     = *reinterpret_cast<const float4*>(&As[k][ty * 8]);
            *reinterpret_cast<float4*>(a + 4) = *reinterpret_cast<const float4*>(&As[k][ty * 8 + 4]);
            *reinterpret_cast<float4*>(b)     = *reinterpret_cast<const float4*>(&Bs[k][tx * 8]);
            *reinterpret_cast<float4*>(b + 4) = *reinterpret_cast<const float4*>(&Bs[k][tx * 8 + 4]);
#pragma unroll
            for (int i = 0; i < 8; ++i)
#pragma unroll
                for (int j = 0; j < 8; ++j)
                    acc[i][j] = fmaf(a[i], b[j], acc[i][j]);
        }
        __syncthreads();
    }

#pragma unroll
    for (int i = 0; i < 8; ++i) {
        float* crow = Cb + (size_t)(ty * 8 + i) * ldc + tx * 8;
        *reinterpret_cast<float4*>(crow) =
            make_float4(acc[i][0], acc[i][1], acc[i][2], acc[i][3]);
        *reinterpret_cast<float4*>(crow + 4) =
            make_float4(acc[i][4], acc[i][5], acc[i][6], acc[i][7]);
    }
}

// Fused QKV projection: one big GEMM over N = 2048 (Q) + 512 (K) + 512 (V)
__global__ __launch_bounds__(256) void qkv_gemm(const float* __restrict__ x,
                                                const float* __restrict__ Wq,
                                                const float* __restrict__ Wk,
                                                const float* __restrict__ Wv) {
    int bm = blockIdx.y * 128;
    int bn = blockIdx.x * 128;
    const float* B;
    float* C;
    int ldc;
    if (bn < 2048) {
        B = Wq + (size_t)bn * DMODEL;
        C = g_q + bn;
        ldc = DMODEL;
    } else if (bn < 2560) {
        int n = bn - 2048;
        B = Wk + (size_t)n * DMODEL;
        C = g_k + n;
        ldc = DKV;
    } else {
        int n = bn - 2560;
        B = Wv + (size_t)n * DMODEL;
        C = g_v + n;
        ldc = DKV;
    }
    gemm_tile(x + (size_t)bm * DMODEL, B, C + (size_t)bm * ldc, DMODEL, ldc);
}

// Output projection: out = g_attn @ Wo^T
__global__ __launch_bounds__(256) void out_gemm(const float* __restrict__ Wo,
                                                float* __restrict__ out) {
    int bm = blockIdx.y * 128;
    int bn = blockIdx.x * 128;
    gemm_tile(g_attn + (size_t)bm * DMODEL,
              Wo + (size_t)bn * DMODEL,
              out + (size_t)bm * DMODEL + bn, DMODEL, DMODEL);
}

// ---------------------------------------------------------------------------
// RoPE in place on g_q (which=0, 32 heads) or g_k (which=1, 8 heads)
// ---------------------------------------------------------------------------
__global__ void rope_kernel(const float* __restrict__ cosb,
                            const float* __restrict__ sinb, int which) {
    float* x = which ? g_k : g_q;
    int H = which ? HKV : HQ;
    int total = TSEQ * H * (DHEAD / 2);
    int idx = blockIdx.x * blockDim.x + threadIdx.x;
    if (idx >= total) return;
    int i = idx & 31;                 // pair index 0..31
    int h = (idx >> 5) % H;
    int t = idx / (32 * H);
    float c = cosb[t * 32 + i];
    float s = sinb[t * 32 + i];
    float* p = x + ((size_t)t * H + h) * DHEAD + 2 * i;
    float x0 = p[0], x1 = p[1];
    p[0] = x0 * c - x1 * s;
    p[1] = x0 * s + x1 * c;
}

// ---------------------------------------------------------------------------
// Flash-style causal GQA attention.
// Grid: (T/128, HQ). Block: 256 threads (16 tx x 16 ty).
// BQ=128 queries, BS=64 keys per tile. Thread tile: 8 q-rows x 4 cols.
// ---------------------------------------------------------------------------
#define BQ 128
#define BS 64
#define SQ_STRIDE 65
constexpr int ATTN_SMEM_FLOATS = BQ * 65 /*Q*/ + BS * 65 /*K*/ + BS * 65 /*V*/ + BQ * 65 /*P*/;
constexpr int ATTN_SMEM_BYTES = ATTN_SMEM_FLOATS * 4;

__global__ __launch_bounds__(256) void attn_kernel() {
    extern __shared__ float sm[];
    float* sQ = sm;                    // [128][65]
    float* sK = sQ + BQ * 65;          // [64][65]
    float* sV = sK + BS * 65;          // [64][65]
    float* sP = sV + BS * 65;          // [128][65]

    int tid = threadIdx.x;
    int qt = blockIdx.x;
    int h = blockIdx.y;
    int kvh = h >> 2;                  // NREP = 4
    int tx = tid & 15;
    int ty = tid >> 4;

    // Load Q tile (128 x 64), row stride DMODEL
    {
        const float* qbase = g_q + (size_t)(qt * BQ) * DMODEL + h * DHEAD;
#pragma unroll
        for (int it = 0; it < 8; ++it) {
            int slot = tid + it * 256;   // 2048 float4 slots
            int row = slot >> 4;
            int c4 = (slot & 15) * 4;
            float4 v = *reinterpret_cast<const float4*>(qbase + (size_t)row * DMODEL + c4);
            float* dst = sQ + row * 65 + c4;
            dst[0] = v.x; dst[1] = v.y; dst[2] = v.z; dst[3] = v.w;
        }
    }

    float m[8], l[8], acc[8][4];
#pragma unroll
    for (int i = 0; i < 8; ++i) {
        m[i] = -1e30f;
        l[i] = 0.0f;
#pragma unroll
        for (int j = 0; j < 4; ++j) acc[i][j] = 0.0f;
    }

    int ntiles = qt * 2 + 2;
    for (int st = 0; st < ntiles; ++st) {
        __syncthreads();   // previous PV done (and Q load on st=0) before overwriting K/V
        // Load K, V tiles (64 x 64), row stride DKV
        {
            const float* kb = g_k + (size_t)(st * BS) * DKV + kvh * DHEAD;
            const float* vb = g_v + (size_t)(st * BS) * DKV + kvh * DHEAD;
#pragma unroll
            for (int it = 0; it < 4; ++it) {
                int slot = tid + it * 256;   // 1024 float4 slots
                int row = slot >> 4;
                int c4 = (slot & 15) * 4;
                float4 vk = *reinterpret_cast<const float4*>(kb + (size_t)row * DKV + c4);
                float* dk = sK + row * 65 + c4;
                dk[0] = vk.x; dk[1] = vk.y; dk[2] = vk.z; dk[3] = vk.w;
                float4 vv = *reinterpret_cast<const float4*>(vb + (size_t)row * DKV + c4);
                float* dv = sV + row * 65 + c4;
                dv[0] = vv.x; dv[1] = vv.y; dv[2] = vv.z; dv[3] = vv.w;
            }
        }
        __syncthreads();

        // Scores: S[8][4] over d = 0..63
        float sc[8][4];
#pragma unroll
        for (int i = 0; i < 8; ++i)
#pragma unroll
            for (int j = 0; j < 4; ++j) sc[i][j] = 0.0f;

#pragma unroll 4
        for (int d = 0; d < DHEAD; ++d) {
            float kf[4];
#pragma unroll
            for (int j = 0; j < 4; ++j) kf[j] = sK[(tx * 4 + j) * 65 + d];
#pragma unroll
            for (int i = 0; i < 8; ++i) {
                float qv = sQ[(ty * 8 + i) * 65 + d];
#pragma unroll
                for (int j = 0; j < 4; ++j) sc[i][j] = fmaf(qv, kf[j], sc[i][j]);
            }
        }

        // Scale + causal mask (only last two tiles can have masked entries)
        const float scale = 0.125f;   // 1/sqrt(64)
        if (st >= 2 * qt) {
#pragma unroll
            for (int i = 0; i < 8; ++i) {
                int q_idx = qt * BQ + ty * 8 + i;
#pragma unroll
                for (int j = 0; j < 4; ++j) {
                    int s_idx = st * BS + tx * 4 + j;
                    sc[i][j] = (s_idx > q_idx) ? -1e30f : sc[i][j] * scale;
                }
            }
        } else {
#pragma unroll
            for (int i = 0; i < 8; ++i)
#pragma unroll
                for (int j = 0; j < 4; ++j) sc[i][j] *= scale;
        }

        // Online softmax per q-row (16 threads with same ty share a row set;
        // they are lanes [0..15] / [16..31] of a warp -> xor shuffles 1,2,4,8)
#pragma unroll
        for (int i = 0; i < 8; ++i) {
            float tmax = fmaxf(fmaxf(sc[i][0], sc[i][1]), fmaxf(sc[i][2], sc[i][3]));
#pragma unroll
            for (int off = 1; off < 16; off <<= 1)
                tmax = fmaxf(tmax, __shfl_xor_sync(0xffffffffu, tmax, off));
            float mn = fmaxf(m[i], tmax);
            float alpha = __expf(m[i] - mn);
            float rs = 0.0f;
#pragma unroll
            for (int j = 0; j < 4; ++j) {
                float p = __expf(sc[i][j] - mn);
                sc[i][j] = p;
                rs += p;
            }
#pragma unroll
            for (int off = 1; off < 16; off <<= 1)
                rs += __shfl_xor_sync(0xffffffffu, rs, off);
            l[i] = l[i] * alpha + rs;
            m[i] = mn;
#pragma unroll
            for (int j = 0; j < 4; ++j) {
                acc[i][j] *= alpha;
                sP[(ty * 8 + i) * 65 + tx * 4 + j] = sc[i][j];
            }
        }
        __syncthreads();

        // PV: O[8 rows][4 dims], dims = tx*4 .. tx*4+3, reduce over s = 0..63
#pragma unroll 2
        for (int s = 0; s < BS; ++s) {
            float vf[4];
#pragma unroll
            for (int j = 0; j < 4; ++j) vf[j] = sV[s * 65 + tx * 4 + j];
#pragma unroll
            for (int i = 0; i < 8; ++i) {
                float pv = sP[(ty * 8 + i) * 65 + s];
#pragma unroll
                for (int j = 0; j < 4; ++j) acc[i][j] = fmaf(pv, vf[j], acc[i][j]);
            }
        }
    }

    // Epilogue: normalize and write (t, h*64 + d) into g_attn
#pragma unroll
    for (int i = 0; i < 8; ++i) {
        float inv = 1.0f / l[i];
        float4 o = make_float4(acc[i][0] * inv, acc[i][1] * inv,
                               acc[i][2] * inv, acc[i][3] * inv);
        *reinterpret_cast<float4*>(
            g_attn + (size_t)(qt * BQ + ty * 8 + i) * DMODEL + h * DHEAD + tx * 4) = o;
    }
}

// ---------------------------------------------------------------------------
extern "C" void kernel_launch(void* const* d_in, const int* in_sizes, int n_in,
                              void* d_out, int out_size) {
    const float* x  = (const float*)d_in[0];
    const float* Wq = (const float*)d_in[1];
    const float* Wk = (const float*)d_in[2];
    const float* Wv = (const float*)d_in[3];
    const float* Wo = (const float*)d_in[4];
    const float* rc = (const float*)d_in[5];
    const float* rs = (const float*)d_in[6];
    // d_in[7] is the causal mask; causality is computed analytically.
    float* out = (float*)d_out;

    cudaFuncSetAttribute(attn_kernel, cudaFuncAttributeMaxDynamicSharedMemorySize,
                         ATTN_SMEM_BYTES);

    // 1) Fused QKV projection: N = 2048 + 512 + 512 = 3072
    qkv_gemm<<<dim3(24, 16), 256>>>(x, Wq, Wk, Wv);

    // 2) RoPE on Q and K
    {
        int totq = TSEQ * HQ * (DHEAD / 2);
        rope_kernel<<<(totq + 255) / 256, 256>>>(rc, rs, 0);
        int totk = TSEQ * HKV * (DHEAD / 2);
        rope_kernel<<<(totk + 255) / 256, 256>>>(rc, rs, 1);
    }

    // 3) Causal GQA attention
    attn_kernel<<<dim3(TSEQ / BQ, HQ), 256, ATTN_SMEM_BYTES>>>();

    // 4) Output projection
    out_gemm<<<dim3(16, 16), 256>>>(Wo, out);
}

// round 4
// speedup vs baseline: 2.7525x; 2.7525x over previous
#include <cuda_runtime.h>
#include <cuda_bf16.h>
#include <math.h>
#include <cstdint>

// Problem constants
#define TSEQ 2048
#define DMODEL 2048
#define HQ 32
#define HKV 8
#define DHEAD 64
#define DKV (HKV * DHEAD)   // 512

// Scratch (device globals: allocation-free rule)
__device__ float g_q[TSEQ * DMODEL];     // (t, hq*64)
__device__ float g_k[TSEQ * DKV];        // (t, hkv*64)
__device__ float g_v[TSEQ * DKV];        // (t, hkv*64)
__device__ float g_attn[TSEQ * DMODEL];  // (t, hq*64)

// ===========================================================================
// Warp-MMA helpers (sm_80+ baseline features; NO tcgen05/TMA — those are
// sm_103a-only and the harness PTX targets plain sm_103).
// ===========================================================================
__device__ __forceinline__ uint32_t smem_u32(const void* p) {
    uint32_t a;
    asm("{ .reg .u64 t; cvta.to.shared.u64 t, %1; cvt.u32.u64 %0, t; }"
        : "=r"(a) : "l"(p));
    return a;
}

__device__ __forceinline__ void ldsm4(uint32_t* r, uint32_t a) {
    asm volatile("ldmatrix.sync.aligned.m8n8.x4.shared.b16 {%0,%1,%2,%3}, [%4];"
                 : "=r"(r[0]), "=r"(r[1]), "=r"(r[2]), "=r"(r[3]) : "r"(a));
}
__device__ __forceinline__ void ldsm4t(uint32_t* r, uint32_t a) {
    asm volatile("ldmatrix.sync.aligned.m8n8.x4.trans.shared.b16 {%0,%1,%2,%3}, [%4];"
                 : "=r"(r[0]), "=r"(r[1]), "=r"(r[2]), "=r"(r[3]) : "r"(a));
}

// D += A * B  (m16n8k16, bf16 in, fp32 acc)
__device__ __forceinline__ void mma_bf16(float* c, const uint32_t* a,
                                         uint32_t b0, uint32_t b1) {
    asm volatile(
        "mma.sync.aligned.m16n8k16.row.col.f32.bf16.bf16.f32 "
        "{%0,%1,%2,%3}, {%4,%5,%6,%7}, {%8,%9}, {%0,%1,%2,%3};"
        : "+f"(c[0]), "+f"(c[1]), "+f"(c[2]), "+f"(c[3])
        : "r"(a[0]), "r"(a[1]), "r"(a[2]), "r"(a[3]), "r"(b0), "r"(b1));
}

__device__ __forceinline__ uint32_t u32of(__nv_bfloat162 h) {
    return *reinterpret_cast<uint32_t*>(&h);
}

// Convert 2 fp32 -> (hi bf16x2, lo bf16x2)
__device__ __forceinline__ void cvt_hilo(float x, float y, uint32_t& hi, uint32_t& lo) {
    __nv_bfloat162 h = __floats2bfloat162_rn(x, y);
    float2 hf = __bfloat1622float2(h);
    __nv_bfloat162 l = __floats2bfloat162_rn(x - hf.x, y - hf.y);
    hi = u32of(h);
    lo = u32of(l);
}

// ===========================================================================
// Projection GEMM: C[128,128] tile of A[M,2048] · B[N,2048]^T, fp32 I/O,
// bf16 hi/lo 3-term HMMA. 256 threads = 8 warps, warp tile 64x32, BK=32.
// ===========================================================================
#define GST 40   // smem row stride in halves (80B: 16B-mult, conflict-free ldsm)
constexpr int GEMM_SMEM_BYTES = 4 * 128 * GST * 2;   // 40960

__device__ void gemm_body(const float* __restrict__ Ab,
                          const float* __restrict__ Bb,
                          float* __restrict__ Cb, int ldc) {
    extern __shared__ uint16_t sm16[];
    uint16_t* sAh = sm16;
    uint16_t* sAl = sAh + 128 * GST;
    uint16_t* sBh = sAl + 128 * GST;
    uint16_t* sBl = sBh + 128 * GST;
    uint32_t aAh = smem_u32(sAh), aAl = smem_u32(sAl);
    uint32_t aBh = smem_u32(sBh), aBl = smem_u32(sBl);

    int tid = threadIdx.x;
    int lane = tid & 31;
    int wid = tid >> 5;
    int m0 = (wid & 1) * 64;
    int n0 = (wid >> 1) * 32;

    float acc[4][4][4];
#pragma unroll
    for (int i = 0; i < 4; ++i)
#pragma unroll
        for (int j = 0; j < 4; ++j)
#pragma unroll
            for (int q = 0; q < 4; ++q) acc[i][j][q] = 0.0f;

    for (int k0 = 0; k0 < 2048; k0 += 32) {
        __syncthreads();
#pragma unroll
        for (int it = 0; it < 4; ++it) {
            int slot = tid + it * 256;          // 1024 slots
            int row = slot >> 3;
            int c4 = (slot & 7) * 4;
            {
                float4 f = *reinterpret_cast<const float4*>(Ab + (size_t)row * 2048 + k0 + c4);
                uint32_t h0, l0, h1, l1;
                cvt_hilo(f.x, f.y, h0, l0);
                cvt_hilo(f.z, f.w, h1, l1);
                *reinterpret_cast<uint32_t*>(sAh + row * GST + c4)     = h0;
                *reinterpret_cast<uint32_t*>(sAh + row * GST + c4 + 2) = h1;
                *reinterpret_cast<uint32_t*>(sAl + row * GST + c4)     = l0;
                *reinterpret_cast<uint32_t*>(sAl + row * GST + c4 + 2) = l1;
            }
            {
                float4 f = *reinterpret_cast<const float4*>(Bb + (size_t)row * 2048 + k0 + c4);
                uint32_t h0, l0, h1, l1;
                cvt_hilo(f.x, f.y, h0, l0);
                cvt_hilo(f.z, f.w, h1, l1);
                *reinterpret_cast<uint32_t*>(sBh + row * GST + c4)     = h0;
                *reinterpret_cast<uint32_t*>(sBh + row * GST + c4 + 2) = h1;
                *reinterpret_cast<uint32_t*>(sBl + row * GST + c4)     = l0;
                *reinterpret_cast<uint32_t*>(sBl + row * GST + c4 + 2) = l1;
            }
        }
        __syncthreads();

#pragma unroll
        for (int kk = 0; kk < 2; ++kk) {
            uint32_t ah[4][4], al[4][4];
            int rA = m0 + (lane & 15);
            int cA = kk * 16 + ((lane >> 4) << 3);
#pragma unroll
            for (int i = 0; i < 4; ++i) {
                ldsm4(ah[i], aAh + (uint32_t)(((rA + 16 * i) * GST + cA) * 2));
                ldsm4(al[i], aAl + (uint32_t)(((rA + 16 * i) * GST + cA) * 2));
            }
            uint32_t bh[2][4], bl[2][4];
            int rB = n0 + (lane & 7) + ((lane >> 3) & 1) * 8;
            int cB = kk * 16 + ((lane >> 4) << 3);
#pragma unroll
            for (int jp = 0; jp < 2; ++jp) {
                ldsm4(bh[jp], aBh + (uint32_t)(((rB + 16 * jp) * GST + cB) * 2));
                ldsm4(bl[jp], aBl + (uint32_t)(((rB + 16 * jp) * GST + cB) * 2));
            }
#pragma unroll
            for (int i = 0; i < 4; ++i)
#pragma unroll
                for (int jp = 0; jp < 2; ++jp) {
                    mma_bf16(acc[i][2 * jp],     ah[i], bh[jp][0], bh[jp][2]);
                    mma_bf16(acc[i][2 * jp],     ah[i], bl[jp][0], bl[jp][2]);
                    mma_bf16(acc[i][2 * jp],     al[i], bh[jp][0], bh[jp][2]);
                    mma_bf16(acc[i][2 * jp + 1], ah[i], bh[jp][1], bh[jp][3]);
                    mma_bf16(acc[i][2 * jp + 1], ah[i], bl[jp][1], bl[jp][3]);
                    mma_bf16(acc[i][2 * jp + 1], al[i], bh[jp][1], bh[jp][3]);
                }
        }
    }

    int r = m0 + (lane >> 2);
    int cq = 2 * (lane & 3);
#pragma unroll
    for (int i = 0; i < 4; ++i)
#pragma unroll
        for (int j = 0; j < 4; ++j) {
            int row = r + 16 * i;
            int col = n0 + 8 * j + cq;
            *reinterpret_cast<float2*>(Cb + (size_t)row * ldc + col) =
                make_float2(acc[i][j][0], acc[i][j][1]);
            *reinterpret_cast<float2*>(Cb + (size_t)(row + 8) * ldc + col) =
                make_float2(acc[i][j][2], acc[i][j][3]);
        }
}

__global__ __launch_bounds__(256) void qkv_hmma(const float* __restrict__ x,
                                                const float* __restrict__ Wq,
                                                const float* __restrict__ Wk,
                                                const float* __restrict__ Wv) {
    int bm = blockIdx.y * 128;
    int bn = blockIdx.x * 128;
    const float* B;
    float* C;
    int ldc;
    if (bn < 2048) {
        B = Wq + (size_t)bn * DMODEL;
        C = g_q + bn;
        ldc = DMODEL;
    } else if (bn < 2560) {
        int n = bn - 2048;
        B = Wk + (size_t)n * DMODEL;
        C = g_k + n;
        ldc = DKV;
    } else {
        int n = bn - 2560;
        B = Wv + (size_t)n * DMODEL;
        C = g_v + n;
        ldc = DKV;
    }
    gemm_body(x + (size_t)bm * DMODEL, B, C + (size_t)bm * ldc, ldc);
}

__global__ __launch_bounds__(256) void out_hmma(const float* __restrict__ Wo,
                                                float* __restrict__ out) {
    int bm = blockIdx.y * 128;
    int bn = blockIdx.x * 128;
    gemm_body(g_attn + (size_t)bm * DMODEL,
              Wo + (size_t)bn * DMODEL,
              out + (size_t)bm * DMODEL + bn, DMODEL);
}

// ---------------------------------------------------------------------------
// RoPE in place on g_q (which=0) or g_k (which=1)
// ---------------------------------------------------------------------------
__global__ void rope_kernel(const float* __restrict__ cosb,
                            const float* __restrict__ sinb, int which) {
    float* x = which ? g_k : g_q;
    int H = which ? HKV : HQ;
    int total = TSEQ * H * (DHEAD / 2);
    int idx = blockIdx.x * blockDim.x + threadIdx.x;
    if (idx >= total) return;
    int i = idx & 31;
    int h = (idx >> 5) % H;
    int t = idx / (32 * H);
    float c = cosb[t * 32 + i];
    float s = sinb[t * 32 + i];
    float* p = x + ((size_t)t * H + h) * DHEAD + 2 * i;
    float x0 = p[0], x1 = p[1];
    p[0] = x0 * c - x1 * s;
    p[1] = x0 * s + x1 * c;
}

// ===========================================================================
// FA2-style causal GQA attention on HMMA.
// Grid (T/64, HQ), 128 threads (4 warps). BQ=64 (16 rows/warp), BS=64.
// QK^T: 3-term hi/lo; P: hi/lo split; PV: 3-term (Phi*Vhi + Plo*Vhi + Phi*Vlo).
// ===========================================================================
#define AST 72   // smem row stride in halves (144B)
constexpr int ATTN_SMEM_BYTES = 6 * 64 * AST * 2;   // 55296

__global__ __launch_bounds__(128) void attn_hmma() {
    extern __shared__ uint16_t sm16[];
    uint16_t* sQh = sm16;
    uint16_t* sQl = sQh + 64 * AST;
    uint16_t* sKh = sQl + 64 * AST;
    uint16_t* sKl = sKh + 64 * AST;
    uint16_t* sVh = sKl + 64 * AST;
    uint16_t* sVl = sVh + 64 * AST;
    uint32_t aQh = smem_u32(sQh), aQl = smem_u32(sQl);
    uint32_t aKh = smem_u32(sKh), aKl = smem_u32(sKl);
    uint32_t aVh = smem_u32(sVh), aVl = smem_u32(sVl);

    int tid = threadIdx.x;
    int lane = tid & 31;
    int w = tid >> 5;
    int qt = blockIdx.x;
    int h = blockIdx.y;
    int kvh = h >> 2;
    const float SCALE = 0.125f;   // 1/sqrt(64)

    // Load + convert Q tile (64 rows x 64 cols)
    {
        const float* qb = g_q + (size_t)(qt * 64) * DMODEL + h * DHEAD;
#pragma unroll
        for (int it = 0; it < 8; ++it) {
            int slot = tid + it * 128;      // 1024 float4 slots
            int row = slot >> 4;
            int c4 = (slot & 15) * 4;
            float4 f = *reinterpret_cast<const float4*>(qb + (size_t)row * DMODEL + c4);
            uint32_t h0, l0, h1, l1;
            cvt_hilo(f.x, f.y, h0, l0);
            cvt_hilo(f.z, f.w, h1, l1);
            *reinterpret_cast<uint32_t*>(sQh + row * AST + c4)     = h0;
            *reinterpret_cast<uint32_t*>(sQh + row * AST + c4 + 2) = h1;
            *reinterpret_cast<uint32_t*>(sQl + row * AST + c4)     = l0;
            *reinterpret_cast<uint32_t*>(sQl + row * AST + c4 + 2) = l1;
        }
    }
    __syncthreads();

    // Q fragments for this warp (rows 16w..16w+15), all 4 k16 steps
    uint32_t qh[4][4], ql[4][4];
    {
        int rQ = 16 * w + (lane & 15);
        int cQ = ((lane >> 4) << 3);
#pragma unroll
        for (int kk = 0; kk < 4; ++kk) {
            ldsm4(qh[kk], aQh + (uint32_t)((rQ * AST + cQ + 16 * kk) * 2));
            ldsm4(ql[kk], aQl + (uint32_t)((rQ * AST + cQ + 16 * kk) * 2));
        }
    }

    float m0 = -1e30f, m1 = -1e30f, l0 = 0.0f, l1 = 0.0f;
    float oac[8][4];
#pragma unroll
    for (int j = 0; j < 8; ++j)
#pragma unroll
        for (int q = 0; q < 4; ++q) oac[j][q] = 0.0f;

    for (int st = 0; st <= qt; ++st) {
        __syncthreads();
        // Load + convert K, V tiles (64 x 64 each)
        {
            const float* kb = g_k + (size_t)(st * 64) * DKV + kvh * DHEAD;
            const float* vb = g_v + (size_t)(st * 64) * DKV + kvh * DHEAD;
#pragma unroll
            for (int it = 0; it < 8; ++it) {
                int slot = tid + it * 128;
                int row = slot >> 4;
                int c4 = (slot & 15) * 4;
                {
                    float4 f = *reinterpret_cast<const float4*>(kb + (size_t)row * DKV + c4);
                    uint32_t h0, lo0, h1, lo1;
                    cvt_hilo(f.x, f.y, h0, lo0);
                    cvt_hilo(f.z, f.w, h1, lo1);
                    *reinterpret_cast<uint32_t*>(sKh + row * AST + c4)     = h0;
                    *reinterpret_cast<uint32_t*>(sKh + row * AST + c4 + 2) = h1;
                    *reinterpret_cast<uint32_t*>(sKl + row * AST + c4)     = lo0;
                    *reinterpret_cast<uint32_t*>(sKl + row * AST + c4 + 2) = lo1;
                }
                {
                    float4 f = *reinterpret_cast<const float4*>(vb + (size_t)row * DKV + c4);
                    uint32_t h0, lo0, h1, lo1;
                    cvt_hilo(f.x, f.y, h0, lo0);
                    cvt_hilo(f.z, f.w, h1, lo1);
                    *reinterpret_cast<uint32_t*>(sVh + row * AST + c4)     = h0;
                    *reinterpret_cast<uint32_t*>(sVh + row * AST + c4 + 2) = h1;
                    *reinterpret_cast<uint32_t*>(sVl + row * AST + c4)     = lo0;
                    *reinterpret_cast<uint32_t*>(sVl + row * AST + c4 + 2) = lo1;
                }
            }
        }
        __syncthreads();

        // ---- S = Q K^T (3-term hi/lo) ----
        float sa[8][4];
#pragma unroll
        for (int j = 0; j < 8; ++j)
#pragma unroll
            for (int q = 0; q < 4; ++q) sa[j][q] = 0.0f;

        int rB = (lane & 7) + ((lane >> 3) & 1) * 8;
        int cB = ((lane >> 4) << 3);
#pragma unroll
        for (int kk = 0; kk < 4; ++kk) {
#pragma unroll
            for (int jp = 0; jp < 4; ++jp) {
                uint32_t kb[4], kbl[4];
                uint32_t off = (uint32_t)(((rB + 16 * jp) * AST + cB + 16 * kk) * 2);
                ldsm4(kb, aKh + off);
                ldsm4(kbl, aKl + off);
                mma_bf16(sa[2 * jp],     qh[kk], kb[0],  kb[2]);
                mma_bf16(sa[2 * jp],     qh[kk], kbl[0], kbl[2]);
                mma_bf16(sa[2 * jp],     ql[kk], kb[0],  kb[2]);
                mma_bf16(sa[2 * jp + 1], qh[kk], kb[1],  kb[3]);
                mma_bf16(sa[2 * jp + 1], qh[kk], kbl[1], kbl[3]);
                mma_bf16(sa[2 * jp + 1], ql[kk], kb[1],  kb[3]);
            }
        }

        // ---- causal mask on diagonal tile ----
        if (st == qt) {
            int rloc = 16 * w + (lane >> 2);
#pragma unroll
            for (int j = 0; j < 8; ++j) {
                int c = 8 * j + 2 * (lane & 3);
                if (c > rloc)         sa[j][0] = -1e30f;
                if (c + 1 > rloc)     sa[j][1] = -1e30f;
                if (c > rloc + 8)     sa[j][2] = -1e30f;
                if (c + 1 > rloc + 8) sa[j][3] = -1e30f;
            }
        }

        // ---- online softmax ----
        float rmax0 = -1e30f, rmax1 = -1e30f;
#pragma unroll
        for (int j = 0; j < 8; ++j) {
            rmax0 = fmaxf(rmax0, fmaxf(sa[j][0], sa[j][1]));
            rmax1 = fmaxf(rmax1, fmaxf(sa[j][2], sa[j][3]));
        }
#pragma unroll
        for (int off = 1; off < 4; off <<= 1) {
            rmax0 = fmaxf(rmax0, __shfl_xor_sync(0xffffffffu, rmax0, off));
            rmax1 = fmaxf(rmax1, __shfl_xor_sync(0xffffffffu, rmax1, off));
        }
        float mn0 = fmaxf(m0, SCALE * rmax0);
        float mn1 = fmaxf(m1, SCALE * rmax1);
        float al0 = __expf(m0 - mn0);
        float al1 = __expf(m1 - mn1);

        // P hi/lo fragments
        uint32_t pa[4][4], pl[4][4];
        float rs0 = 0.0f, rs1 = 0.0f;
#pragma unroll
        for (int j = 0; j < 8; ++j) {
            float p0 = __expf(fmaf(SCALE, sa[j][0], -mn0));
            float p1 = __expf(fmaf(SCALE, sa[j][1], -mn0));
            float p2 = __expf(fmaf(SCALE, sa[j][2], -mn1));
            float p3 = __expf(fmaf(SCALE, sa[j][3], -mn1));
            rs0 += p0 + p1;
            rs1 += p2 + p3;
            uint32_t h01, l01, h23, l23;
            cvt_hilo(p0, p1, h01, l01);
            cvt_hilo(p2, p3, h23, l23);
            pa[j >> 1][(j & 1) ? 2 : 0] = h01;
            pa[j >> 1][(j & 1) ? 3 : 1] = h23;
            pl[j >> 1][(j & 1) ? 2 : 0] = l01;
            pl[j >> 1][(j & 1) ? 3 : 1] = l23;
        }
#pragma unroll
        for (int off = 1; off < 4; off <<= 1) {
            rs0 += __shfl_xor_sync(0xffffffffu, rs0, off);
            rs1 += __shfl_xor_sync(0xffffffffu, rs1, off);
        }
        l0 = l0 * al0 + rs0;
        l1 = l1 * al1 + rs1;
        m0 = mn0;
        m1 = mn1;
#pragma unroll
        for (int j = 0; j < 8; ++j) {
            oac[j][0] *= al0;
            oac[j][1] *= al0;
            oac[j][2] *= al1;
            oac[j][3] *= al1;
        }

        // ---- O += P V (3-term: Phi*Vhi + Plo*Vhi + Phi*Vlo) ----
#pragma unroll
        for (int ks = 0; ks < 4; ++ks) {
#pragma unroll
            for (int jp = 0; jp < 4; ++jp) {
                uint32_t vh[4], vl[4];
                int row = 16 * ks + (lane & 7) + ((lane >> 3) & 1) * 8;
                int col = 16 * jp + ((lane >> 4) << 3);
                uint32_t off = (uint32_t)((row * AST + col) * 2);
                ldsm4t(vh, aVh + off);
                ldsm4t(vl, aVl + off);
                mma_bf16(oac[2 * jp],     pa[ks], vh[0], vh[1]);
                mma_bf16(oac[2 * jp],     pl[ks], vh[0], vh[1]);
                mma_bf16(oac[2 * jp],     pa[ks], vl[0], vl[1]);
                mma_bf16(oac[2 * jp + 1], pa[ks], vh[2], vh[3]);
                mma_bf16(oac[2 * jp + 1], pl[ks], vh[2], vh[3]);
                mma_bf16(oac[2 * jp + 1], pa[ks], vl[2], vl[3]);
            }
        }
    }

    // Epilogue: normalize and store to g_attn
    float inv0 = 1.0f / l0;
    float inv1 = 1.0f / l1;
    int row = qt * 64 + 16 * w + (lane >> 2);
    float* ob = g_attn + (size_t)row * DMODEL + h * DHEAD;
#pragma unroll
    for (int j = 0; j < 8; ++j) {
        int col = 8 * j + 2 * (lane & 3);
        *reinterpret_cast<float2*>(ob + col) =
            make_float2(oac[j][0] * inv0, oac[j][1] * inv0);
        *reinterpret_cast<float2*>(ob + (size_t)8 * DMODEL + col) =
            make_float2(oac[j][2] * inv1, oac[j][3] * inv1);
    }
}

// ---------------------------------------------------------------------------
extern "C" void kernel_launch(void* const* d_in, const int* in_sizes, int n_in,
                              void* d_out, int out_size) {
    const float* x  = (const float*)d_in[0];
    const float* Wq = (const float*)d_in[1];
    const float* Wk = (const float*)d_in[2];
    const float* Wv = (const float*)d_in[3];
    const float* Wo = (const float*)d_in[4];
    const float* rc = (const float*)d_in[5];
    const float* rs = (const float*)d_in[6];
    float* out = (float*)d_out;

    static bool attrs_set = false;
    if (!attrs_set) {
        cudaFuncSetAttribute(attn_hmma, cudaFuncAttributeMaxDynamicSharedMemorySize,
                             ATTN_SMEM_BYTES);
        cudaFuncSetAttribute(qkv_hmma, cudaFuncAttributeMaxDynamicSharedMemorySize,
                             GEMM_SMEM_BYTES);
        cudaFuncSetAttribute(out_hmma, cudaFuncAttributeMaxDynamicSharedMemorySize,
                             GEMM_SMEM_BYTES);
        attrs_set = true;
    }

    // 1) Fused QKV projection (HMMA, bf16 hi/lo 3-term)
    qkv_hmma<<<dim3(24, 16), 256, GEMM_SMEM_BYTES>>>(x, Wq, Wk, Wv);

    // 2) RoPE on Q and K
    {
        int totq = TSEQ * HQ * (DHEAD / 2);
        rope_kernel<<<(totq + 255) / 256, 256>>>(rc, rs, 0);
        int totk = TSEQ * HKV * (DHEAD / 2);
        rope_kernel<<<(totk + 255) / 256, 256>>>(rc, rs, 1);
    }

    // 3) Causal GQA attention (HMMA)
    attn_hmma<<<dim3(TSEQ / 64, HQ), 128, ATTN_SMEM_BYTES>>>();

    // 4) Output projection (HMMA)
    out_hmma<<<dim3(16, 16), 256, GEMM_SMEM_BYTES>>>(Wo, out);
}